// round 1
// baseline (speedup 1.0000x reference)
#include <cuda_runtime.h>
#include <cstdint>

#define DB 64
#define DS 2048
#define DI 64
#define DH 128
#define DM (DB*DS)   // 131072 rows

// Scratch (allocation-free rule: __device__ globals)
__device__ float g_wx0[DB*DS*DH];
__device__ float g_out0[DB*DS*DH];
__device__ float g_wx1[DB*DS*DH];

typedef unsigned long long u64;

// ---- packed f32x2 helpers (sm_100a) ----
__device__ __forceinline__ u64 ffma2(u64 a, u64 b, u64 c){
    u64 d; asm("fma.rn.f32x2 %0, %1, %2, %3;" : "=l"(d) : "l"(a), "l"(b), "l"(c)); return d;
}
__device__ __forceinline__ u64 fadd2(u64 a, u64 b){
    u64 d; asm("add.rn.f32x2 %0, %1, %2;" : "=l"(d) : "l"(a), "l"(b)); return d;
}
__device__ __forceinline__ u64 dup2(float x){
    u64 d; asm("mov.b64 %0, {%1, %2};" : "=l"(d) : "f"(x), "f"(x)); return d;
}
__device__ __forceinline__ float2 unp2(u64 v){
    float lo, hi; asm("mov.b64 {%0, %1}, %2;" : "=f"(lo), "=f"(hi) : "l"(v));
    return make_float2(lo, hi);
}

// ---- fast-but-accurate-enough activations (err ~1e-6 rel) ----
__device__ __forceinline__ float sigm(float x){
    float e = __expf(fminf(-x, 30.f));          // clamp keeps denominator < 1e13 (safe for __fdividef)
    return __fdividef(1.f, 1.f + e);
}
__device__ __forceinline__ float tanh_f(float x){
    float xc = fminf(fmaxf(x, -15.f), 15.f);    // tanh(15) == 1.0f in fp32
    float e  = __expf(2.f * xc);
    return __fdividef(e - 1.f, e + 1.f);
}

// ============================================================================
// GEMM: OUT[row, 0:128] = X[row, 0:K] @ W[K, 128]. One row per thread.
// W staged in dynamic smem, broadcast LDS.64 pairs; fp32x2 FMA (2x pipe rate).
// ============================================================================
template<int K>
__global__ void __launch_bounds__(256, 1) gemm_rows(
    const float* __restrict__ X, const float* __restrict__ W, float* __restrict__ OUT)
{
    extern __shared__ float ws[];
    for (int i = threadIdx.x; i < K*DH/4; i += 256)
        reinterpret_cast<float4*>(ws)[i] = reinterpret_cast<const float4*>(W)[i];
    __syncthreads();

    int row = blockIdx.x * 256 + threadIdx.x;
    const float* xr = X + (size_t)row * K;
    float xv[K];
    #pragma unroll
    for (int i = 0; i < K/4; i++){
        float4 v = reinterpret_cast<const float4*>(xr)[i];
        xv[4*i] = v.x; xv[4*i+1] = v.y; xv[4*i+2] = v.z; xv[4*i+3] = v.w;
    }

    const u64* wsu = reinterpret_cast<const u64*>(ws);
    float* outr = OUT + (size_t)row * DH;

    #pragma unroll 1
    for (int cb = 0; cb < 16; cb++){              // 8 output cols per block
        u64 a0 = 0, a1 = 0, a2 = 0, a3 = 0;
        #pragma unroll 16
        for (int k = 0; k < K; k++){
            u64 xd = dup2(xv[k]);
            const u64* wr = wsu + k*(DH/2) + cb*4;
            a0 = ffma2(xd, wr[0], a0);
            a1 = ffma2(xd, wr[1], a1);
            a2 = ffma2(xd, wr[2], a2);
            a3 = ffma2(xd, wr[3], a3);
        }
        float2 r0 = unp2(a0), r1 = unp2(a1), r2 = unp2(a2), r3 = unp2(a3);
        reinterpret_cast<float4*>(outr)[cb*2]     = make_float4(r0.x, r0.y, r1.x, r1.y);
        reinterpret_cast<float4*>(outr)[cb*2 + 1] = make_float4(r2.x, r2.y, r3.x, r3.y);
    }
}

// ============================================================================
// Recurrent scan: one CTA per batch row. u column-pairs live in registers
// (32 x u64 per thread; thread = (colpair c2, k-quarter kq)). Hidden state in
// smem duplicated as {h[k],h[k]} so broadcast LDS.64 feeds fma.rn.f32x2
// directly. Ping-pong h buffers; 4-way k-split partials reduced through smem.
// ============================================================================
__global__ void __launch_bounds__(256, 1) scan_layer(
    const float* __restrict__ wx, const float* __restrict__ u,
    const float* __restrict__ bg, const float* __restrict__ bu,
    const float* __restrict__ zeta, const float* __restrict__ nu,
    const float* __restrict__ lambd, const float* __restrict__ gamma,
    float* __restrict__ out_seq, float* __restrict__ hT)
{
    __shared__ __align__(16) float hdup[2][2*DH];   // ping-pong, duplicated pairs
    __shared__ __align__(16) float part[4][DH];     // k-quarter partials

    const int tid = threadIdx.x;
    const int b   = blockIdx.x;
    const int c2  = tid & 63;      // output column pair -> cols (2*c2, 2*c2+1)
    const int kq  = tid >> 6;      // k-quarter: k in [32*kq, 32*kq+32)
    const int j0  = 2 * c2;

    // u[k, j0], u[k, j0+1] contiguous in row-major u -> load as one 8B word
    u64 uk[32];
    #pragma unroll
    for (int kk = 0; kk < 32; kk++)
        uk[kk] = *reinterpret_cast<const u64*>(u + (size_t)(kq*32 + kk)*DH + j0);

    for (int i = tid; i < 2*2*DH; i += 256) (&hdup[0][0])[i] = 0.f;

    const float sz   = sigm(zeta[0]);
    const float sn   = sigm(nu[0]);
    const float gc   = fminf(fmaxf(gamma[0], 0.f), 1.f);
    const float cadd = (1.f - gc) * lambd[0];

    const float* wxb  = wx      + (size_t)b * DS * DH;
    float*       outb = out_seq + (size_t)b * DS * DH;

    float bgj = 0.f, buj = 0.f, hold = 0.f, wxA = 0.f, wxB = 0.f;
    if (tid < DH){
        bgj = bg[tid]; buj = bu[tid];
        wxA = wxb[tid];                 // wx[s=0]
        wxB = wxb[DH + tid];            // wx[s=1]
    }
    __syncthreads();

    #pragma unroll 1
    for (int s = 0; s < DS; s++){
        const int cur = s & 1;
        // ---- matvec phase: partial (h @ u) for 2 cols over 32 k's ----
        const u64* hb = reinterpret_cast<const u64*>(&hdup[cur][kq * 64]);
        u64 a0 = 0, a1 = 0, a2 = 0, a3 = 0;
        #pragma unroll
        for (int t = 0; t < 8; t++){
            a0 = ffma2(hb[4*t + 0], uk[4*t + 0], a0);
            a1 = ffma2(hb[4*t + 1], uk[4*t + 1], a1);
            a2 = ffma2(hb[4*t + 2], uk[4*t + 2], a2);
            a3 = ffma2(hb[4*t + 3], uk[4*t + 3], a3);
        }
        a0 = fadd2(fadd2(a0, a1), fadd2(a2, a3));
        *reinterpret_cast<u64*>(&part[kq][j0]) = a0;
        __syncthreads();

        // ---- gate phase: thread j < 128 owns output j ----
        if (tid < DH){
            float pre = wxA + ((part[0][tid] + part[1][tid]) + (part[2][tid] + part[3][tid]));
            float z   = sigm(pre + bgj);
            float hh  = tanh_f(pre + buj);
            float hn  = z * hold + (sz * (1.f - z) + sn) * hh;
            float hc  = __fmaf_rn(gc, hn, cadd);
            outb[(size_t)s * DH + tid] = hc;
            hold = hc;
            reinterpret_cast<float2*>(&hdup[cur ^ 1][0])[tid] = make_float2(hc, hc);
            // depth-2 wx prefetch
            wxA = wxB;
            wxB = (s + 2 < DS) ? __ldg(&wxb[(size_t)(s + 2) * DH + tid]) : 0.f;
        }
        __syncthreads();
    }
    if (tid < DH) hT[(size_t)b * DH + tid] = hold;
}

// ============================================================================
extern "C" void kernel_launch(void* const* d_in, const int* in_sizes, int n_in,
                              void* d_out, int out_size)
{
    const float* x      = (const float*)d_in[0];
    const float* w0     = (const float*)d_in[1];
    const float* u0     = (const float*)d_in[2];
    const float* bg0    = (const float*)d_in[3];
    const float* bu0    = (const float*)d_in[4];
    const float* zeta0  = (const float*)d_in[5];
    const float* nu0    = (const float*)d_in[6];
    const float* lambd0 = (const float*)d_in[7];
    const float* gamma0 = (const float*)d_in[8];
    const float* w1     = (const float*)d_in[9];
    const float* u1     = (const float*)d_in[10];
    const float* bg1    = (const float*)d_in[11];
    const float* bu1    = (const float*)d_in[12];
    const float* zeta1  = (const float*)d_in[13];
    const float* nu1    = (const float*)d_in[14];
    const float* lambd1 = (const float*)d_in[15];
    const float* gamma1 = (const float*)d_in[16];
    (void)in_sizes; (void)n_in; (void)out_size;

    float* out = (float*)d_out;                    // out1: [B, S, H]
    float* hT0 = out + (size_t)DB * DS * DH;       // h_n[0]: [B, H]
    float* hT1 = hT0 + (size_t)DB * DH;            // h_n[1]: [B, H]

    void *p0, *p1, *p2;
    cudaGetSymbolAddress(&p0, g_wx0);
    cudaGetSymbolAddress(&p1, g_out0);
    cudaGetSymbolAddress(&p2, g_wx1);
    float* wx0p  = (float*)p0;
    float* out0p = (float*)p1;
    float* wx1p  = (float*)p2;

    cudaFuncSetAttribute(gemm_rows<DI>, cudaFuncAttributeMaxDynamicSharedMemorySize, DI*DH*4);
    cudaFuncSetAttribute(gemm_rows<DH>, cudaFuncAttributeMaxDynamicSharedMemorySize, DH*DH*4);

    // layer 0
    gemm_rows<DI><<<DM/256, 256, DI*DH*4>>>(x, w0, wx0p);
    scan_layer<<<DB, 256>>>(wx0p, u0, bg0, bu0, zeta0, nu0, lambd0, gamma0, out0p, hT0);
    // layer 1
    gemm_rows<DH><<<DM/256, 256, DH*DH*4>>>(out0p, w1, wx1p);
    scan_layer<<<DB, 256>>>(wx1p, u1, bg1, bu1, zeta1, nu1, lambd1, gamma1, out, hT1);
}

// round 2
// speedup vs baseline: 1.5819x; 1.5819x over previous
#include <cuda_runtime.h>
#include <cstdint>

#define DB 64
#define DS 2048
#define DI 64
#define DH 128

typedef unsigned long long u64;

// ---------------- scratch (__device__ globals, allocation-free rule) --------
__device__ float g_out0[DB * DS * DH];   // layer-0 outputs (h0 history)
__device__ float g_wx1a[DB * DS * 64];   // out0 @ w1[:,0:64], computed by producer
__device__ int   g_prog[DB * 32];        // per-batch progress flags (padded)

// ---------------- packed f32x2 helpers --------------------------------------
__device__ __forceinline__ u64 ffma2(u64 a, u64 b, u64 c) {
    u64 d; asm("fma.rn.f32x2 %0, %1, %2, %3;" : "=l"(d) : "l"(a), "l"(b), "l"(c)); return d;
}
__device__ __forceinline__ u64 fadd2(u64 a, u64 b) {
    u64 d; asm("add.rn.f32x2 %0, %1, %2;" : "=l"(d) : "l"(a), "l"(b)); return d;
}
__device__ __forceinline__ u64 dup2(float x) {
    u64 d; asm("mov.b64 %0, {%1, %2};" : "=l"(d) : "f"(x), "f"(x)); return d;
}

// ---------------- activations (fp32, err ~1e-7) ------------------------------
__device__ __forceinline__ float sigm(float x) {
    float e = __expf(fminf(-x, 30.f));
    return __fdividef(1.f, 1.f + e);
}
__device__ __forceinline__ float tanh_f(float x) {
    float xc = fminf(fmaxf(x, -15.f), 15.f);
    float e  = __expf(2.f * xc);
    return __fdividef(e - 1.f, e + 1.f);
}

// ---------------- release/acquire flag ops ----------------------------------
__device__ __forceinline__ int ld_acq(const int* p) {
    int v; asm volatile("ld.acquire.gpu.b32 %0, [%1];" : "=r"(v) : "l"(p)); return v;
}
__device__ __forceinline__ void st_rel(int* p, int v) {
    asm volatile("st.release.gpu.b32 [%0], %1;" :: "l"(p), "r"(v));
}
__device__ __forceinline__ void spin_ge(const int* p, int target) {
    while (ld_acq(p) < target) __nanosleep(40);
}

// ---------------- shared-memory layouts --------------------------------------
struct SmemP {                     // producer (layer 0)
    u64 vdup[2][192];              // v = [x_t(64) ; h0_t(128)], duplicated pairs
    u64 partA[8][64];              // partials for pre0 (128 cols)
    u64 partB[8][32];              // partials for wx1a (64 cols)
};
struct SmemC {                     // consumer (layer 1)
    u64 vdup[2][256];              // v = [out0_t(128) ; h1_t(128)]
    u64 partY[8][32];              // cols 64..127 (w1b + u1)
    u64 partX[8][32];              // cols 0..63   (u1 only)
};
union __align__(16) SmemU { SmemP p; SmemC c; };

__global__ void reset_kernel() {
    if (threadIdx.x < DB) g_prog[threadIdx.x * 32] = 0;
}

// ============================================================================
// Producer: layer-0 scan + fused x@w0 + fused wx1a = out0@w1[:,0:64]
// ============================================================================
__device__ __forceinline__ void producer(
    SmemP& sm,
    const float* __restrict__ x,    // + b*DS*DI
    const float* __restrict__ w0, const float* __restrict__ u0,
    const float* __restrict__ w1,
    const float* __restrict__ bg, const float* __restrict__ bu,
    const float* __restrict__ zeta, const float* __restrict__ nu,
    const float* __restrict__ lambd, const float* __restrict__ gamma,
    float* __restrict__ out0,       // + b*DS*DH
    float* __restrict__ wx1,        // + b*DS*64
    float* __restrict__ hT,         // + b*DH
    int* prog)
{
    const int tid = threadIdx.x;
    const int kq  = tid >> 5;       // warp = k-quarter (8-way)
    const int c   = tid & 31;       // lane = column-pair index

    // Block A weights: stacked M = [w0 (64x128) ; u0 (128x128)], rows 192.
    // Lane c owns column pairs c (cols 2c,2c+1) and c+32 (cols 64+2c,64+2c+1).
    u64 ukA0[24], ukA1[24];
    #pragma unroll
    for (int kk = 0; kk < 24; kk++) {
        int r = kq * 24 + kk;
        const float* row = (r < 64) ? (w0 + (size_t)r * DH) : (u0 + (size_t)(r - 64) * DH);
        ukA0[kk] = *reinterpret_cast<const u64*>(row + 2 * c);
        ukA1[kk] = *reinterpret_cast<const u64*>(row + 64 + 2 * c);
    }
    // Block B weights: w1[:,0:64]; k over h slots (64..191 -> h index kq*16+kk)
    u64 ukB[16];
    #pragma unroll
    for (int kk = 0; kk < 16; kk++)
        ukB[kk] = *reinterpret_cast<const u64*>(w1 + (size_t)(kq * 16 + kk) * DH + 2 * c);

    const float sz   = sigm(zeta[0]);
    const float sn   = sigm(nu[0]);
    const float gc   = fminf(fmaxf(gamma[0], 0.f), 1.f);
    const float cadd = (1.f - gc) * lambd[0];

    float bgj = 0.f, buj = 0.f, hold = 0.f, xB = 0.f;
    if (tid < DH) {
        bgj = bg[tid]; buj = bu[tid];
        sm.vdup[0][64 + tid] = 0ull;                 // h0 = 0
        if (tid < DI) {
            sm.vdup[0][tid] = dup2(x[tid]);          // x[0]
            xB = x[DI + tid];                        // x[1]
        }
    }
    __syncthreads();

    const float* pf  = reinterpret_cast<const float*>(sm.partA);  // [8][128]
    const float* pfB = reinterpret_cast<const float*>(sm.partB);  // [8][64]

    #pragma unroll 1
    for (int s = 0; s < DS; s++) {
        const int cur = s & 1, nxt = cur ^ 1;
        const u64* vd = sm.vdup[cur];

        // -------- matvec phase (all 8 warps) --------
        u64 a0e = 0, a0o = 0, a1e = 0, a1o = 0;
        #pragma unroll
        for (int t = 0; t < 12; t++) {
            ulonglong2 q = *reinterpret_cast<const ulonglong2*>(&vd[kq * 24 + 2 * t]);
            a0e = ffma2(q.x, ukA0[2 * t], a0e);
            a1e = ffma2(q.x, ukA1[2 * t], a1e);
            a0o = ffma2(q.y, ukA0[2 * t + 1], a0o);
            a1o = ffma2(q.y, ukA1[2 * t + 1], a1o);
        }
        u64 b0 = 0, b1 = 0;
        #pragma unroll
        for (int t = 0; t < 8; t++) {
            ulonglong2 q = *reinterpret_cast<const ulonglong2*>(&vd[64 + kq * 16 + 2 * t]);
            b0 = ffma2(q.x, ukB[2 * t], b0);
            b1 = ffma2(q.y, ukB[2 * t + 1], b1);
        }
        sm.partA[kq][c]      = fadd2(a0e, a0o);
        sm.partA[kq][c + 32] = fadd2(a1e, a1o);
        sm.partB[kq][c]      = fadd2(b0, b1);
        __syncthreads();

        // -------- gate phase --------
        if (tid < DH) {
            float p0 = pf[tid],           p1 = pf[128 + tid],
                  p2 = pf[256 + tid],     p3 = pf[384 + tid],
                  p4 = pf[512 + tid],     p5 = pf[640 + tid],
                  p6 = pf[768 + tid],     p7 = pf[896 + tid];
            float pre = ((p0 + p1) + (p2 + p3)) + ((p4 + p5) + (p6 + p7));
            float zg = sigm(pre + bgj);
            float hh = tanh_f(pre + buj);
            float hn = zg * hold + (sz * (1.f - zg) + sn) * hh;
            float hc = __fmaf_rn(gc, hn, cadd);
            out0[(size_t)s * DH + tid] = hc;
            hold = hc;
            sm.vdup[nxt][64 + tid] = dup2(hc);
            if (tid < DI) {
                sm.vdup[nxt][tid] = dup2(xB);
                xB = (s + 2 < DS) ? x[(size_t)(s + 2) * DI + tid] : 0.f;
            }
        } else if (tid < 192) {
            int j2 = tid - 128;
            float q0 = pfB[j2],        q1 = pfB[64 + j2],
                  q2 = pfB[128 + j2],  q3 = pfB[192 + j2],
                  q4 = pfB[256 + j2],  q5 = pfB[320 + j2],
                  q6 = pfB[384 + j2],  q7 = pfB[448 + j2];
            float w = ((q0 + q1) + (q2 + q3)) + ((q4 + q5) + (q6 + q7));
            if (s > 0) wx1[(size_t)(s - 1) * 64 + j2] = w;   // wx1a for step s-1
        }
        if ((s & 15) == 15) __threadfence();
        __syncthreads();
        if ((s & 15) == 15 && tid == 0) st_rel(prog, s);     // wx1a count = s
    }

    // -------- epilogue: wx1a[DS-1] from final h --------
    {
        const u64* vd = sm.vdup[0];   // DS even -> final h lives in buffer 0
        u64 b0 = 0, b1 = 0;
        #pragma unroll
        for (int t = 0; t < 8; t++) {
            ulonglong2 q = *reinterpret_cast<const ulonglong2*>(&vd[64 + kq * 16 + 2 * t]);
            b0 = ffma2(q.x, ukB[2 * t], b0);
            b1 = ffma2(q.y, ukB[2 * t + 1], b1);
        }
        sm.partB[kq][c] = fadd2(b0, b1);
        __syncthreads();
        if (tid >= 128 && tid < 192) {
            int j2 = tid - 128;
            float q0 = pfB[j2],        q1 = pfB[64 + j2],
                  q2 = pfB[128 + j2],  q3 = pfB[192 + j2],
                  q4 = pfB[256 + j2],  q5 = pfB[320 + j2],
                  q6 = pfB[384 + j2],  q7 = pfB[448 + j2];
            wx1[(size_t)(DS - 1) * 64 + j2] =
                ((q0 + q1) + (q2 + q3)) + ((q4 + q5) + (q6 + q7));
        }
        if (tid < DH) hT[tid] = hold;
        __threadfence();
        __syncthreads();
        if (tid == 0) st_rel(prog, DS);
    }
}

// ============================================================================
// Consumer: layer-1 scan; v = [out0_t(128) ; h1_t(128)]
//   cols 0..63  : pre = wx1a[t] (from producer) + h1 @ u1[:,0:64]
//   cols 64..127: pre = out0_t @ w1[:,64:128] + h1 @ u1[:,64:128]
// ============================================================================
__device__ __forceinline__ void consumer(
    SmemC& sm,
    const float* __restrict__ out0,  // + b*DS*DH (from producer)
    const float* __restrict__ wx1,   // + b*DS*64
    const float* __restrict__ w1, const float* __restrict__ u1,
    const float* __restrict__ bg, const float* __restrict__ bu,
    const float* __restrict__ zeta, const float* __restrict__ nu,
    const float* __restrict__ lambd, const float* __restrict__ gamma,
    float* __restrict__ out1,        // + b*DS*DH
    float* __restrict__ hT,          // + b*DH
    const int* prog)
{
    const int tid = threadIdx.x;
    const int kq  = tid >> 5;
    const int c   = tid & 31;

    // Block Y: cols 64..127 over stacked [w1 ; u1] (256 rows).
    u64 ukY0[16], ukY1[16];
    #pragma unroll
    for (int kk = 0; kk < 32; kk++) {
        int r = kq * 32 + kk;
        const float* row = (r < DH) ? (w1 + (size_t)r * DH) : (u1 + (size_t)(r - DH) * DH);
        u64 v = *reinterpret_cast<const u64*>(row + 64 + 2 * c);
        if (kk & 1) ukY1[kk >> 1] = v; else ukY0[kk >> 1] = v;
    }
    // Block X: cols 0..63 over u1 only (h slots 128..255 -> u1 row kq*16+kk).
    u64 ukX[16];
    #pragma unroll
    for (int kk = 0; kk < 16; kk++)
        ukX[kk] = *reinterpret_cast<const u64*>(u1 + (size_t)(kq * 16 + kk) * DH + 2 * c);

    const float sz   = sigm(zeta[0]);
    const float sn   = sigm(nu[0]);
    const float gc   = fminf(fmaxf(gamma[0], 0.f), 1.f);
    const float cadd = (1.f - gc) * lambd[0];

    // Wait for pipeline fill (out0[0..18], wx1a[0..17])
    if (tid == 0) { spin_ge(prog, (18 < DS) ? 18 : DS); __threadfence(); }
    __syncthreads();

    float bgj = 0.f, buj = 0.f, hold = 0.f, oB = 0.f, wxA = 0.f, wxB = 0.f;
    if (tid < DH) {
        bgj = bg[tid]; buj = bu[tid];
        sm.vdup[0][tid]       = dup2(out0[tid]);     // out0[0]
        sm.vdup[0][128 + tid] = 0ull;                // h1 = 0
        oB = out0[DH + tid];                         // out0[1]
        if (tid < 64) { wxA = wx1[tid]; wxB = wx1[64 + tid]; }
    }
    __syncthreads();

    const float* pfY = reinterpret_cast<const float*>(sm.partY);  // [8][64]
    const float* pfX = reinterpret_cast<const float*>(sm.partX);  // [8][64]

    #pragma unroll 1
    for (int s = 0; s < DS; s++) {
        if ((s & 15) == 0 && s) {
            if (tid == 0) {
                int tgt = s + 18; if (tgt > DS) tgt = DS;
                spin_ge(prog, tgt);
                __threadfence();
            }
            __syncthreads();
        }
        const int cur = s & 1, nxt = cur ^ 1;
        const u64* vd = sm.vdup[cur];

        // -------- matvec phase --------
        u64 ye = 0, yo = 0;
        #pragma unroll
        for (int t = 0; t < 16; t++) {
            ulonglong2 q = *reinterpret_cast<const ulonglong2*>(&vd[kq * 32 + 2 * t]);
            ye = ffma2(q.x, ukY0[t], ye);
            yo = ffma2(q.y, ukY1[t], yo);
        }
        u64 xe = 0, xo = 0;
        #pragma unroll
        for (int t = 0; t < 8; t++) {
            ulonglong2 q = *reinterpret_cast<const ulonglong2*>(&vd[128 + kq * 16 + 2 * t]);
            xe = ffma2(q.x, ukX[2 * t], xe);
            xo = ffma2(q.y, ukX[2 * t + 1], xo);
        }
        sm.partY[kq][c] = fadd2(ye, yo);
        sm.partX[kq][c] = fadd2(xe, xo);
        __syncthreads();

        // -------- gate phase --------
        if (tid < DH) {
            float pre;
            if (tid < 64) {
                float q0 = pfX[tid],        q1 = pfX[64 + tid],
                      q2 = pfX[128 + tid],  q3 = pfX[192 + tid],
                      q4 = pfX[256 + tid],  q5 = pfX[320 + tid],
                      q6 = pfX[384 + tid],  q7 = pfX[448 + tid];
                pre = wxA + (((q0 + q1) + (q2 + q3)) + ((q4 + q5) + (q6 + q7)));
            } else {
                int j2 = tid - 64;
                float q0 = pfY[j2],        q1 = pfY[64 + j2],
                      q2 = pfY[128 + j2],  q3 = pfY[192 + j2],
                      q4 = pfY[256 + j2],  q5 = pfY[320 + j2],
                      q6 = pfY[384 + j2],  q7 = pfY[448 + j2];
                pre = ((q0 + q1) + (q2 + q3)) + ((q4 + q5) + (q6 + q7));
            }
            float zg = sigm(pre + bgj);
            float hh = tanh_f(pre + buj);
            float hn = zg * hold + (sz * (1.f - zg) + sn) * hh;
            float hc = __fmaf_rn(gc, hn, cadd);
            out1[(size_t)s * DH + tid] = hc;
            hold = hc;
            sm.vdup[nxt][128 + tid] = dup2(hc);
            sm.vdup[nxt][tid]       = dup2(oB);
            oB = (s + 2 < DS) ? out0[(size_t)(s + 2) * DH + tid] : 0.f;
            if (tid < 64) {
                wxA = wxB;
                wxB = (s + 2 < DS) ? wx1[(size_t)(s + 2) * 64 + tid] : 0.f;
            }
        }
        __syncthreads();
    }
    if (tid < DH) hT[tid] = hold;
}

// ============================================================================
__global__ void __launch_bounds__(256, 1) fused_kernel(
    const float* __restrict__ x,
    const float* __restrict__ w0, const float* __restrict__ u0,
    const float* __restrict__ bg0, const float* __restrict__ bu0,
    const float* __restrict__ zeta0, const float* __restrict__ nu0,
    const float* __restrict__ lambd0, const float* __restrict__ gamma0,
    const float* __restrict__ w1, const float* __restrict__ u1,
    const float* __restrict__ bg1, const float* __restrict__ bu1,
    const float* __restrict__ zeta1, const float* __restrict__ nu1,
    const float* __restrict__ lambd1, const float* __restrict__ gamma1,
    float* __restrict__ out1, float* __restrict__ hT0, float* __restrict__ hT1)
{
    __shared__ SmemU sm;
    const int layer = blockIdx.x >> 6;
    const int b     = blockIdx.x & 63;

    float* out0b = g_out0 + (size_t)b * DS * DH;
    float* wx1b  = g_wx1a + (size_t)b * DS * 64;
    int*   progb = g_prog + b * 32;

    if (layer == 0) {
        producer(sm.p, x + (size_t)b * DS * DI, w0, u0, w1,
                 bg0, bu0, zeta0, nu0, lambd0, gamma0,
                 out0b, wx1b, hT0 + (size_t)b * DH, progb);
    } else {
        consumer(sm.c, out0b, wx1b, w1, u1,
                 bg1, bu1, zeta1, nu1, lambd1, gamma1,
                 out1 + (size_t)b * DS * DH, hT1 + (size_t)b * DH, progb);
    }
}

// ============================================================================
extern "C" void kernel_launch(void* const* d_in, const int* in_sizes, int n_in,
                              void* d_out, int out_size)
{
    const float* x      = (const float*)d_in[0];
    const float* w0     = (const float*)d_in[1];
    const float* u0     = (const float*)d_in[2];
    const float* bg0    = (const float*)d_in[3];
    const float* bu0    = (const float*)d_in[4];
    const float* zeta0  = (const float*)d_in[5];
    const float* nu0    = (const float*)d_in[6];
    const float* lambd0 = (const float*)d_in[7];
    const float* gamma0 = (const float*)d_in[8];
    const float* w1     = (const float*)d_in[9];
    const float* u1     = (const float*)d_in[10];
    const float* bg1    = (const float*)d_in[11];
    const float* bu1    = (const float*)d_in[12];
    const float* zeta1  = (const float*)d_in[13];
    const float* nu1    = (const float*)d_in[14];
    const float* lambd1 = (const float*)d_in[15];
    const float* gamma1 = (const float*)d_in[16];
    (void)in_sizes; (void)n_in; (void)out_size;

    float* out = (float*)d_out;                    // out1: [B, S, H]
    float* hT0 = out + (size_t)DB * DS * DH;       // h_n[0]
    float* hT1 = hT0 + (size_t)DB * DH;            // h_n[1]

    reset_kernel<<<1, 64>>>();
    fused_kernel<<<2 * DB, 256>>>(x, w0, u0, bg0, bu0, zeta0, nu0, lambd0, gamma0,
                                  w1, u1, bg1, bu1, zeta1, nu1, lambd1, gamma1,
                                  out, hT0, hT1);
}